// round 17
// baseline (speedup 1.0000x reference)
#include <cuda_runtime.h>

#define Bn 64
#define Dd 32
#define Hh 48
#define Ww 48
#define NA (Dd*Hh*Ww)        /* 73728 anchors per batch */
#define TOPK 60
#define NMS_TOPK 20
#define THRESH 0.15f
#define NMS_T 0.05f
#define NBINS 4096
#define NTA 256              /* kscan threads */
#define NT 1024              /* kselect threads */
#define SLICES 8
#define SF4 (NA/4/SLICES)    /* 2304 float4 per slice */
#define FPT (SF4/NTA)        /* 9 float4 per thread */
#define SLOTA 64             /* per-slice capacity (mean 17, >10 sigma) */
#define AWSLOT 32            /* per-warp staging in kscan */
#define CAND_FB 2304
#define T_RAW 2.9f

__device__ unsigned long long g_scand[Bn][SLICES][SLOTA];
__device__ int g_scnt[Bn][SLICES];

__device__ __forceinline__ unsigned fkey(float f) {
    unsigned u = __float_as_uint(f);
    return u ^ ((u & 0x80000000u) ? 0xFFFFFFFFu : 0x80000000u);
}
__device__ __forceinline__ float finv(unsigned k) {
    unsigned u = (k & 0x80000000u) ? (k ^ 0x80000000u) : ~k;
    return __uint_as_float(u);
}

// ================= kernel 1: full-chip sparse scan, deterministic slots ========
__global__ __launch_bounds__(NTA)
void kscan(const float* __restrict__ Cls, float* __restrict__ out)
{
    const int s   = blockIdx.x;
    const int b   = blockIdx.y;
    const int tid = threadIdx.x;
    const int wid = tid >> 5;            // 8 warps
    const int lid = tid & 31;

    __shared__ int wcnt[8];
    __shared__ int woff[8];
    __shared__ int s_tot;
    __shared__ int s_ovf;
    __shared__ unsigned long long stg[8][AWSLOT];

    if (tid < 8) wcnt[tid] = 0;

    const float4* c4 = (const float4*)(Cls + (size_t)b * NA);
    const int base = s * SF4 + tid;

    float4 q[FPT];
    #pragma unroll
    for (int j = 0; j < FPT; j++) q[j] = c4[base + j * NTA];

    // slice-0 CTA prefills this batch's output with -1 while loads fly
    if (s == 0) {
        float* ob = out + (size_t)b * TOPK * 8;
        for (int i = tid; i < TOPK * 8; i += NTA) ob[i] = -1.0f;
    }
    __syncthreads();

    {
        unsigned hm = 0;
        #pragma unroll
        for (int j = 0; j < FPT; j++) {
            float mx = fmaxf(fmaxf(q[j].x, q[j].y), fmaxf(q[j].z, q[j].w));
            hm |= (mx > T_RAW) ? (1u << j) : 0u;
        }
        if (hm) {                                        // rare
            #pragma unroll
            for (int j = 0; j < FPT; j++) {
                if (hm & (1u << j)) {
                    int gi = base + j * NTA;
                    #pragma unroll
                    for (int k = 0; k < 4; k++) {
                        float f = (k == 0) ? q[j].x : (k == 1) ? q[j].y
                                : (k == 2) ? q[j].z : q[j].w;
                        if (f > T_RAW) {
                            int off = atomicAdd(&wcnt[wid], 1);
                            if (off < AWSLOT) {
                                unsigned idx = (unsigned)(gi * 4 + k);
                                stg[wid][off] =
                                    ((unsigned long long)fkey(f) << 32) | (unsigned)(~idx);
                            }
                        }
                    }
                }
            }
        }
    }
    __syncthreads();

    if (tid == 0) {
        int acc = 0, ovf = 0;
        #pragma unroll
        for (int w = 0; w < 8; w++) {
            int cw = wcnt[w];
            if (cw > AWSLOT) ovf = 1;
            woff[w] = acc;
            acc += min(cw, AWSLOT);
        }
        s_tot = acc;
        s_ovf = ovf | (acc > SLOTA);
        g_scnt[b][s] = (ovf || acc > SLOTA) ? (1 << 20) : acc;  // poison on overflow
    }
    __syncthreads();

    if (!s_ovf) {
        int cw = min(wcnt[wid], AWSLOT);
        if (lid < cw) {
            int d = woff[wid] + lid;
            if (d < SLOTA) g_scand[b][s][d] = stg[wid][lid];
        }
    }
}

// ================= kernel 2: per-batch select + NMS + write ====================
__global__ __launch_bounds__(NT, 1)
void kselect(const float* __restrict__ Cls,
             const float* __restrict__ Shp,
             const float* __restrict__ Off,
             float* __restrict__ out)
{
    const int b   = blockIdx.x;
    const int tid = threadIdx.x;
    const int lid = tid & 31;

    __shared__ int s_n[SLICES];
    __shared__ int s_off[SLICES];
    __shared__ int s_cnt;
    __shared__ int s_bad;
    __shared__ __align__(16) union UU {
        unsigned hist[NBINS];                 /* 16 KB, fallback only */
        unsigned long long cand[CAND_FB];
    } u;
    __shared__ int partial[NT];
    __shared__ int thr_bin;
    __shared__ int cand_cnt;
    __shared__ float s_score[TOPK];
    __shared__ float s_ctr[TOPK][3];
    __shared__ float s_ext[TOPK][3];
    __shared__ float s_lo[TOPK][3];
    __shared__ float s_hi[TOPK][3];
    __shared__ float s_vol[TOPK];
    __shared__ unsigned char s_valid[TOPK];
    __shared__ unsigned long long s_mask[TOPK];
    __shared__ unsigned long long s_keep;

    const float4* c4 = (const float4*)(Cls + (size_t)b * NA);
    float* ob = out + (size_t)b * TOPK * 8;

    if (tid < TOPK) s_mask[tid] = 0ull;
    if (tid == 0) {
        int acc = 0, bad = 0;
        #pragma unroll
        for (int s = 0; s < SLICES; s++) {
            int n = g_scnt[b][s];
            if (n > SLOTA) { bad = 1; n = 0; }
            s_n[s] = n;
            s_off[s] = acc;
            acc += n;
        }
        s_cnt = acc;
        s_bad = bad | (acc < TOPK) | (acc > NT);
    }
    __syncthreads();

    int c = s_cnt;
    const bool fast = !s_bad;

    if (fast) {
        // gather slots -> contiguous smem (one predicated load per thread)
        if (tid < SLICES * SLOTA) {
            int s = tid >> 6;            // /SLOTA
            int j = tid & (SLOTA - 1);   // %SLOTA
            if (j < s_n[s]) u.cand[s_off[s] + j] = g_scand[b][s][j];
        }
        if (tid == 0) u.cand[c] = 0ull;  // pad for vectorized rank
        __syncthreads();

        // ---------- rank-select top-60, gather boxes ----------
        if (tid < c) {
            unsigned long long k0 = u.cand[tid];

            unsigned idx = ~(unsigned)(k0 & 0xFFFFFFFFull);
            int z = (int)idx / (Hh * Ww);
            int rem = (int)idx % (Hh * Ww);
            float az = (float)z, ay = (float)(rem / Ww), ax = (float)(rem % Ww);
            size_t base3 = (size_t)b * 3 * NA + idx;
            float o0 = Off[base3], o1 = Off[base3 + NA], o2 = Off[base3 + 2 * NA];
            float h0 = Shp[base3], h1 = Shp[base3 + NA], h2 = Shp[base3 + 2 * NA];

            int r0 = 0;
            const ulonglong2* cv = (const ulonglong2*)u.cand;
            int half = (c + 1) >> 1;
            #pragma unroll 4
            for (int j = 0; j < half; j++) {
                ulonglong2 p = cv[j];
                r0 += (p.x > k0) ? 1 : 0;
                r0 += (p.y > k0) ? 1 : 0;
            }

            if (r0 < TOPK) {
                float raw = finv((unsigned)(k0 >> 32));
                float sc  = 1.0f / (1.0f + __expf(-raw));
                s_score[r0] = sc;
                s_valid[r0] = (sc > THRESH) ? 1 : 0;
                s_ctr[r0][0] = (az + o0) * 2.0f;         // stride = (2,2,2)
                s_ctr[r0][1] = (ay + o1) * 2.0f;
                s_ctr[r0][2] = (ax + o2) * 2.0f;
                s_ext[r0][0] = 2.0f * h0;
                s_ext[r0][1] = 2.0f * h1;
                s_ext[r0][2] = 2.0f * h2;
            }
        }
        __syncthreads();
    } else {
        // -------- exact histogram fallback over the whole batch (never hit) ------
        for (int i = tid; i < NBINS; i += NT) u.hist[i] = 0u;
        if (tid == 0) { thr_bin = 0; cand_cnt = 0; }
        __syncthreads();
        for (int i = tid; i < NA / 4; i += NT) {
            float4 v = c4[i];
            #pragma unroll
            for (int k = 0; k < 4; k++) {
                float f = (k == 0) ? v.x : (k == 1) ? v.y : (k == 2) ? v.z : v.w;
                int bin = (int)(fkey(f) >> 20);
                unsigned m = __match_any_sync(0xFFFFFFFFu, bin);
                if (lid == (__ffs(m) - 1))
                    atomicAdd(&u.hist[bin], (unsigned)__popc(m));
            }
        }
        __syncthreads();
        const int BPT = NBINS / NT;                      // 4
        int hbase = tid * BPT;
        int loc = 0;
        #pragma unroll
        for (int j = 0; j < BPT; j++) loc += (int)u.hist[hbase + j];
        partial[tid] = loc;
        __syncthreads();
        if (tid == 0) {
            int run = 0;
            for (int t = NT - 1; t >= 0; t--) { int p = partial[t]; partial[t] = run; run += p; }
        }
        __syncthreads();
        {
            int cum_above = partial[tid];
            if (cum_above < TOPK && cum_above + loc >= TOPK) {
                int cum = cum_above;
                for (int j = BPT - 1; j >= 0; j--) {
                    cum += (int)u.hist[hbase + j];
                    if (cum >= TOPK) { thr_bin = hbase + j; break; }
                }
            }
        }
        __syncthreads();
        const unsigned klow = (unsigned)thr_bin << 20;
        __syncthreads();                                 // done with hist before reuse
        for (int i = tid; i < NA / 4; i += NT) {
            float4 v = c4[i];
            #pragma unroll
            for (int k = 0; k < 4; k++) {
                float f = (k == 0) ? v.x : (k == 1) ? v.y : (k == 2) ? v.z : v.w;
                unsigned key = fkey(f);
                if (key >= klow) {
                    int pos = atomicAdd(&cand_cnt, 1);
                    if (pos < CAND_FB) {
                        unsigned idx = (unsigned)(i * 4 + k);
                        u.cand[pos] = ((unsigned long long)key << 32) | (unsigned)(~idx);
                    }
                }
            }
        }
        __syncthreads();

        const int cf = min(cand_cnt, CAND_FB);
        for (int i = tid; i < cf; i += NT) {
            unsigned long long ki = u.cand[i];
            int rank = 0;
            for (int j = 0; j < cf; j++) rank += (u.cand[j] > ki) ? 1 : 0;
            if (rank < TOPK) {
                unsigned key = (unsigned)(ki >> 32);
                unsigned idx = ~(unsigned)(ki & 0xFFFFFFFFull);
                float raw = finv(key);
                float sc  = 1.0f / (1.0f + expf(-raw));
                s_score[rank] = sc;
                s_valid[rank] = (sc > THRESH) ? 1 : 0;
                int z   = (int)idx / (Hh * Ww);
                int rem = (int)idx % (Hh * Ww);
                int y   = rem / Ww;
                int x   = rem % Ww;
                size_t base3 = (size_t)b * 3 * NA + idx;
                float o0 = Off[base3], o1 = Off[base3 + NA], o2 = Off[base3 + 2 * NA];
                float h0 = Shp[base3], h1 = Shp[base3 + NA], h2 = Shp[base3 + 2 * NA];
                s_ctr[rank][0] = ((float)z + o0) * 2.0f;
                s_ctr[rank][1] = ((float)y + o1) * 2.0f;
                s_ctr[rank][2] = ((float)x + o2) * 2.0f;
                s_ext[rank][0] = 2.0f * h0;
                s_ext[rank][1] = 2.0f * h1;
                s_ext[rank][2] = 2.0f * h2;
            }
        }
        __syncthreads();
        // refill output in fallback (kscan prefilled, but stay exact)
        if (tid < TOPK * 8) ob[tid] = -1.0f;
        __syncthreads();
    }

    // ---- precompute lo/hi/vol per box (one thread per box) ----
    if (tid < TOPK) {
        #pragma unroll
        for (int d = 0; d < 3; d++) {
            float cc = s_ctr[tid][d], ee = s_ext[tid][d];
            s_lo[tid][d] = cc - 0.5f * ee;
            s_hi[tid][d] = cc + 0.5f * ee;
        }
        s_vol[tid] = s_ext[tid][0] * s_ext[tid][1] * s_ext[tid][2];
    }
    __syncthreads();

    // ---- IoU > NMS_T bitmask: 17 strips x 4 cols per row ----
    {
        int i = tid % TOPK;           // row
        int qd = tid / TOPK;          // strip (tid < 1020 -> qd < 17)
        if (qd < 17) {
            float li0 = s_lo[i][0], li1 = s_lo[i][1], li2 = s_lo[i][2];
            float hi0 = s_hi[i][0], hi1 = s_hi[i][1], hi2 = s_hi[i][2];
            float vi  = s_vol[i];
            unsigned long long m = 0ull;
            int j0 = qd * 4;
            #pragma unroll
            for (int t = 0; t < 4; t++) {
                int j = j0 + t;
                if (j < TOPK) {
                    float d0 = fminf(hi0, s_hi[j][0]) - fmaxf(li0, s_lo[j][0]);
                    float d1 = fminf(hi1, s_hi[j][1]) - fmaxf(li1, s_lo[j][1]);
                    float d2 = fminf(hi2, s_hi[j][2]) - fmaxf(li2, s_lo[j][2]);
                    float inter = fmaxf(d0, 0.0f) * fmaxf(d1, 0.0f) * fmaxf(d2, 0.0f);
                    float un  = vi + s_vol[j] - inter;
                    float iou = inter / fmaxf(un, 1e-8f);
                    if (iou > NMS_T) m |= (1ull << j);
                }
            }
            if (m) atomicOr(&s_mask[i], m);
        }
    }
    __syncthreads();

    // ---- greedy NMS on a u64 mask ----
    if (tid == 0) {
        unsigned long long km = 0ull;
        #pragma unroll 4
        for (int i = 0; i < TOPK; i++)
            if (s_valid[i] && !(s_mask[i] & km)) km |= (1ull << i);
        s_keep = km;
    }
    __syncthreads();

    // ---- write kept rows at their rank (output already -1-filled) ----
    if (tid < TOPK) {
        unsigned long long km = s_keep;
        if ((km >> tid) & 1ull) {
            int rk = __popcll(km & ((1ull << tid) - 1ull));
            if (rk < NMS_TOPK) {
                float* row = ob + (size_t)rk * 8;
                row[0] = 1.0f;
                row[1] = s_score[tid];
                row[2] = s_ctr[tid][0];
                row[3] = s_ctr[tid][1];
                row[4] = s_ctr[tid][2];
                row[5] = s_ext[tid][0];
                row[6] = s_ext[tid][1];
                row[7] = s_ext[tid][2];
            }
        }
    }
}

extern "C" void kernel_launch(void* const* d_in, const int* in_sizes, int n_in,
                              void* d_out, int out_size)
{
    const float* Cls = (const float*)d_in[0];
    const float* Shp = (const float*)d_in[1];
    const float* Off = (const float*)d_in[2];
    float* out = (float*)d_out;

    dim3 gridA(SLICES, Bn);              // 512 CTAs: full-chip scan
    kscan<<<gridA, NTA>>>(Cls, out);
    kselect<<<Bn, NT>>>(Cls, Shp, Off, out);   // graph edge = the only sync
}